// round 16
// baseline (speedup 1.0000x reference)
#include <cuda_runtime.h>
#include <math.h>

#define ESL    4096
#define BATCH  64
#define EHS    256
#define GROUPS 8                   // batch groups of 8 (one warp per batch)
#define SLICESS 72                 // s-slices
#define NBLK   (GROUPS * SLICESS)  // 576 blocks ~= one wave at 4 blocks/SM

// per-(batch, slice) partials: g_pc[b][slice][ch]  (4.7 MB, L2-hot when read)
__device__ float g_pc[BATCH * SLICESS * EHS];
__device__ float g_pz[BATCH * SLICESS];
__device__ int   g_cnt[BATCH];     // zero-init; tail warp resets each run

__device__ __forceinline__ float dot4(float4 a, float4 b) {
    return a.x*b.x + a.y*b.y + a.z*b.z + a.w*b.w;
}

__global__ __launch_bounds__(256, 4)
void attn_fused(const float* __restrict__ si,   // (1,64,256)
                const float* __restrict__ h,    // (4096,64,256)
                const float* __restrict__ W,    // (1,512) [Wd|We]
                const float* __restrict__ bias, // (1,)
                float* __restrict__ out)        // (1,64,256)
{
    const int group = blockIdx.x % GROUPS;
    const int slice = blockIdx.x / GROUPS;      // 0..71
    const int w     = threadIdx.x >> 5;
    const int lane  = threadIdx.x & 31;
    const int b     = group * 8 + w;            // this warp's batch

    const float4* We4 = (const float4*)(W + EHS);
    const float4 we0 = We4[lane];
    const float4 we1 = We4[lane + 32];

    // d = dot(si[b], Wd) + bias (per-warp batch)
    const float4* Wd4 = (const float4*)W;
    const float4* si4 = (const float4*)(si + b * EHS);
    float4 a0 = si4[lane], a1 = si4[lane + 32];
    float4 w0 = Wd4[lane], w1 = Wd4[lane + 32];
    float d = dot4(a0, w0) + dot4(a1, w1);
    #pragma unroll
    for (int o = 16; o; o >>= 1) d += __shfl_xor_sync(0xFFFFFFFFu, d, o);
    d += bias[0];

    // slice's contiguous s-range: first 64 slices get 57 rows, last 8 get 56
    const int s0  = slice * 56 + (slice < 64 ? slice : 64);
    const int cnt = 56 + (slice < 64 ? 1 : 0);

    const size_t rs = (size_t)BATCH * EHS;
    const float* hb = h + (size_t)b * EHS;

    float Z = 0.0f;
    float4 c0 = make_float4(0.f, 0.f, 0.f, 0.f);
    float4 c1 = make_float4(0.f, 0.f, 0.f, 0.f);

    // 2-deep register prefetch pipeline over contiguous s-range
    const float4* p0 = (const float4*)(hb + (size_t)s0 * rs);
    float4 f0 = p0[lane], f1 = p0[lane + 32];
    const float4* p1 = (const float4*)(hb + (size_t)(s0 + 1) * rs);
    float4 g0 = p1[lane], g1 = p1[lane + 32];

    for (int i = 0; i < cnt; i++) {
        const float4 u0 = f0, u1 = f1;
        f0 = g0; f1 = g1;
        if (i + 2 < cnt) {
            const float4* pn = (const float4*)(hb + (size_t)(s0 + i + 2) * rs);
            g0 = pn[lane]; g1 = pn[lane + 32];
        }

        float e = dot4(u0, we0) + dot4(u1, we1);
        #pragma unroll
        for (int o = 16; o; o >>= 1) e += __shfl_xor_sync(0xFFFFFFFFu, e, o);
        const float q = __expf(fmaxf(e + d, 0.0f));
        Z += q;
        c0.x = fmaf(q, u0.x, c0.x); c0.y = fmaf(q, u0.y, c0.y);
        c0.z = fmaf(q, u0.z, c0.z); c0.w = fmaf(q, u0.w, c0.w);
        c1.x = fmaf(q, u1.x, c1.x); c1.y = fmaf(q, u1.y, c1.y);
        c1.z = fmaf(q, u1.z, c1.z); c1.w = fmaf(q, u1.w, c1.w);
    }

    // ---- store this warp's partial (no block combine needed) ----
    float4* dst = (float4*)(g_pc + ((size_t)b * SLICESS + slice) * EHS);
    dst[lane]      = c0;
    dst[lane + 32] = c1;
    if (lane == 0) g_pz[b * SLICESS + slice] = Z;

    // ---- warp-local fused tail: 72nd arrival for b reduces its partials ----
    __threadfence();
    unsigned last = 0;
    if (lane == 0) last = (atomicAdd(&g_cnt[b], 1) == SLICESS - 1);
    last = __shfl_sync(0xFFFFFFFFu, last, 0);
    if (last) {
        __threadfence();   // acquire: all 72 partials visible
        const float4* src = (const float4*)(g_pc + (size_t)b * SLICESS * EHS);
        float4 t0 = make_float4(0.f, 0.f, 0.f, 0.f);
        float4 t1 = make_float4(0.f, 0.f, 0.f, 0.f);
        #pragma unroll 8
        for (int s = 0; s < SLICESS; s++) {
            const float4 u0 = __ldcg(src + s * (EHS / 4) + lane);
            const float4 u1 = __ldcg(src + s * (EHS / 4) + lane + 32);
            t0.x += u0.x; t0.y += u0.y; t0.z += u0.z; t0.w += u0.w;
            t1.x += u1.x; t1.y += u1.y; t1.z += u1.z; t1.w += u1.w;
        }
        float z = 0.0f;
        for (int s = lane; s < SLICESS; s += 32) z += __ldcg(&g_pz[b * SLICESS + s]);
        #pragma unroll
        for (int o = 16; o; o >>= 1) z += __shfl_xor_sync(0xFFFFFFFFu, z, o);

        const float inv = 1.0f / z;
        t0.x *= inv; t0.y *= inv; t0.z *= inv; t0.w *= inv;
        t1.x *= inv; t1.y *= inv; t1.z *= inv; t1.w *= inv;
        float4* o4 = (float4*)(out + (size_t)b * EHS);
        o4[lane]      = t0;
        o4[lane + 32] = t1;
        if (lane == 0) g_cnt[b] = 0;   // reset for next graph replay
    }
}

extern "C" void kernel_launch(void* const* d_in, const int* in_sizes, int n_in,
                              void* d_out, int out_size)
{
    const float* si   = (const float*)d_in[0];  // (1,64,256)
    const float* h    = (const float*)d_in[1];  // (4096,64,256)
    const float* W    = (const float*)d_in[2];  // (1,512)
    const float* bias = (const float*)d_in[3];  // (1,)
    float* out = (float*)d_out;                 // (1,64,256)

    attn_fused<<<NBLK, 256>>>(si, h, W, bias, out);
}

// round 17
// speedup vs baseline: 1.1083x; 1.1083x over previous
#include <cuda_runtime.h>
#include <math.h>

#define ESL    4096
#define BATCH  64
#define EHS    256
#define SLICES 14
#define NBLK   (BATCH * SLICES)   // 896 blocks ~= one wave at 6 blocks/SM
#define NSTREAM 112               // warp-streams per batch (14 slices * 8 warps)

// block-level partials: g_pc[b][slice][ch], g_pz[b][slice]  (~917 KB -> L2-hot)
__device__ float g_pc[BATCH * SLICES * EHS];
__device__ float g_pz[BATCH * SLICES];
__device__ int   g_cnt[BATCH];    // zero-init; consumer resets each run

__device__ __forceinline__ float dot4(float4 a, float4 b) {
    return a.x*b.x + a.y*b.y + a.z*b.z + a.w*b.w;
}

__global__ __launch_bounds__(256, 6)
void attn_fused(const float* __restrict__ si,   // (1,64,256)
                const float* __restrict__ h,    // (4096,64,256)
                const float* __restrict__ W,    // (1,512) [Wd|We]
                const float* __restrict__ bias, // (1,)
                float* __restrict__ out)        // (1,64,256)
{
    const int b     = blockIdx.x & 63;
    const int slice = blockIdx.x >> 6;          // 0..13
    const int tid   = threadIdx.x;
    const int w     = tid >> 5;
    const int lane  = tid & 31;

    const float4* We4 = (const float4*)(W + EHS);
    const float4 we0 = We4[lane];
    const float4 we1 = We4[lane + 32];

    // d = dot(si[b], Wd) + bias
    const float4* Wd4 = (const float4*)W;
    const float4* si4 = (const float4*)(si + b * EHS);
    float4 a0 = si4[lane], a1 = si4[lane + 32];
    float4 w0 = Wd4[lane], w1 = Wd4[lane + 32];
    float d = dot4(a0, w0) + dot4(a1, w1);
    #pragma unroll
    for (int o = 16; o; o >>= 1) d += __shfl_xor_sync(0xFFFFFFFFu, d, o);
    d += bias[0];

    const size_t rs = (size_t)BATCH * EHS;      // floats between s and s+1
    const float* hb = h + (size_t)b * EHS;
    const int j = slice * 8 + w;                // warp stream id, 0..111

    float Z = 0.0f;
    float4 c0 = make_float4(0.f, 0.f, 0.f, 0.f);
    float4 c1 = make_float4(0.f, 0.f, 0.f, 0.f);

    // paired-row loop: rows j + 112k; two rows in flight per iteration
    int s = j;
    for (; s + NSTREAM < ESL; s += 2 * NSTREAM) {
        const float4* p0 = (const float4*)(hb + (size_t)s * rs);
        const float4* p1 = (const float4*)(hb + (size_t)(s + NSTREAM) * rs);
        const float4 h00 = p0[lane], h01 = p0[lane + 32];
        const float4 h10 = p1[lane], h11 = p1[lane + 32];

        float e0 = dot4(h00, we0) + dot4(h01, we1);
        float e1 = dot4(h10, we0) + dot4(h11, we1);
        #pragma unroll
        for (int o = 16; o; o >>= 1) {
            e0 += __shfl_xor_sync(0xFFFFFFFFu, e0, o);
            e1 += __shfl_xor_sync(0xFFFFFFFFu, e1, o);
        }
        const float q0 = __expf(fmaxf(e0 + d, 0.0f));
        const float q1 = __expf(fmaxf(e1 + d, 0.0f));
        Z += q0 + q1;
        c0.x = fmaf(q0, h00.x, fmaf(q1, h10.x, c0.x));
        c0.y = fmaf(q0, h00.y, fmaf(q1, h10.y, c0.y));
        c0.z = fmaf(q0, h00.z, fmaf(q1, h10.z, c0.z));
        c0.w = fmaf(q0, h00.w, fmaf(q1, h10.w, c0.w));
        c1.x = fmaf(q0, h01.x, fmaf(q1, h11.x, c1.x));
        c1.y = fmaf(q0, h01.y, fmaf(q1, h11.y, c1.y));
        c1.z = fmaf(q0, h01.z, fmaf(q1, h11.z, c1.z));
        c1.w = fmaf(q0, h01.w, fmaf(q1, h11.w, c1.w));
    }
    if (s < ESL) {   // leftover single row
        const float4* p0 = (const float4*)(hb + (size_t)s * rs);
        const float4 h00 = p0[lane], h01 = p0[lane + 32];
        float e0 = dot4(h00, we0) + dot4(h01, we1);
        #pragma unroll
        for (int o = 16; o; o >>= 1) e0 += __shfl_xor_sync(0xFFFFFFFFu, e0, o);
        const float q0 = __expf(fmaxf(e0 + d, 0.0f));
        Z += q0;
        c0.x = fmaf(q0, h00.x, c0.x); c0.y = fmaf(q0, h00.y, c0.y);
        c0.z = fmaf(q0, h00.z, c0.z); c0.w = fmaf(q0, h00.w, c0.w);
        c1.x = fmaf(q0, h01.x, c1.x); c1.y = fmaf(q0, h01.y, c1.y);
        c1.z = fmaf(q0, h01.z, c1.z); c1.w = fmaf(q0, h01.w, c1.w);
    }

    // ---- block combine: 8 warps -> 1 partial ----
    __shared__ __align__(16) float4 s_c4[8][EHS / 4];   // 8 KB
    __shared__ float s_z[8];
    __shared__ bool  s_last;
    s_c4[w][lane]      = c0;
    s_c4[w][lane + 32] = c1;
    if (lane == 0) s_z[w] = Z;
    __syncthreads();

    if (tid < 64) {
        float4 acc = s_c4[0][tid];
        #pragma unroll
        for (int p = 1; p < 8; p++) {
            float4 u = s_c4[p][tid];
            acc.x += u.x; acc.y += u.y; acc.z += u.z; acc.w += u.w;
        }
        ((float4*)(g_pc + ((size_t)b * SLICES + slice) * EHS))[tid] = acc;
    }
    if (tid == 0) {
        float zt = 0.0f;
        #pragma unroll
        for (int p = 0; p < 8; p++) zt += s_z[p];
        g_pz[b * SLICES + slice] = zt;
    }

    // ---- fused tail: last block per batch reduces its 14 partials ----
    __threadfence();
    __syncthreads();
    if (tid == 0) s_last = (atomicAdd(&g_cnt[b], 1) == SLICES - 1);
    __syncthreads();
    if (s_last) {
        __threadfence();   // acquire: all partials visible
        float z = 0.0f;
        #pragma unroll
        for (int p = 0; p < SLICES; p++) z += g_pz[b * SLICES + p];
        float c = 0.0f;
        #pragma unroll
        for (int p = 0; p < SLICES; p++)
            c += g_pc[((size_t)b * SLICES + p) * EHS + tid];
        out[b * EHS + tid] = c / z;
        if (tid == 0) g_cnt[b] = 0;   // reset for next graph replay
    }
}

extern "C" void kernel_launch(void* const* d_in, const int* in_sizes, int n_in,
                              void* d_out, int out_size)
{
    const float* si   = (const float*)d_in[0];  // (1,64,256)
    const float* h    = (const float*)d_in[1];  // (4096,64,256)
    const float* W    = (const float*)d_in[2];  // (1,512)
    const float* bias = (const float*)d_in[3];  // (1,)
    float* out = (float*)d_out;                 // (1,64,256)

    attn_fused<<<NBLK, 256>>>(si, h, W, bias, out);
}